// round 9
// baseline (speedup 1.0000x reference)
#include <cuda_runtime.h>
#include <cuda_bf16.h>
#include <cstdint>

#define NNODES 50000
#define NEDGES 640000
#define HID    128
#define CLS    64
#define NT     391            // ceil(50000/128) M-tiles

#define SCAN_BLK 1024
#define NSCANBLK ((NNODES + SCAN_BLK - 1) / SCAN_BLK)   // 49

typedef unsigned long long u64;

// ---------------- scratch (static __device__, no allocation) ----------------
__device__ float g_h[NNODES * HID];                        // fp32 z (ping)
__device__ float g_h2[NNODES * HID];                       // fp32 z (pong)
__device__ __align__(16) unsigned char g_Whi[3 * 32768 + 16384]; // W^T tiles
__device__ __align__(16) unsigned char g_Wlo[3 * 32768 + 16384];
__device__ float g_dinv[NNODES];
__device__ int   g_cnt[NNODES];      // zero-initialized; invariant: zero at launch start
__device__ int   g_rowptr[NNODES + 1];
__device__ int   g_pos[NNODES];
__device__ int   g_bsum[NSCANBLK];
__device__ __align__(8) int2 g_edge[NEDGES];   // fused (srow, dinv-bits)

// ---------------- helpers ----------------
__device__ __forceinline__ uint32_t smem_to_u32(const void* p) {
    uint32_t a;
    asm("{ .reg .u64 t; cvta.to.shared.u64 t, %1; cvt.u32.u64 %0, t; }" : "=r"(a) : "l"(p));
    return a;
}

// tile layout: 128-bf16 rows (256B), 16B chunks XOR-swizzled by row for
// conflict-free ldmatrix. byte(r, k) = r*256 + 16*((k>>3) ^ (r&7)) + (k&7)*2
__device__ __forceinline__ uint32_t tile_off(int r, int k) {
    return (uint32_t)(r * 256 + 16 * (((k >> 3) ^ (r & 7))) + (k & 7) * 2);
}

__device__ __forceinline__ void ldsm4(uint32_t* r, uint32_t addr) {
    asm volatile("ldmatrix.sync.aligned.m8n8.x4.shared.b16 {%0,%1,%2,%3}, [%4];"
                 : "=r"(r[0]), "=r"(r[1]), "=r"(r[2]), "=r"(r[3]) : "r"(addr));
}
__device__ __forceinline__ void mma16816(float* c, const uint32_t* a, const uint32_t* b) {
    asm volatile("mma.sync.aligned.m16n8k16.row.col.f32.bf16.bf16.f32 "
                 "{%0,%1,%2,%3}, {%4,%5,%6,%7}, {%8,%9}, {%0,%1,%2,%3};"
                 : "+f"(c[0]), "+f"(c[1]), "+f"(c[2]), "+f"(c[3])
                 : "r"(a[0]), "r"(a[1]), "r"(a[2]), "r"(a[3]), "r"(b[0]), "r"(b[1]));
}

// split one float4 into hi/lo bf16x4 and store 8B each
__device__ __forceinline__ void split_store(char* hiB, char* loB, uint32_t off, float4 v) {
    __nv_bfloat162 h0 = __floats2bfloat162_rn(v.x, v.y);
    __nv_bfloat162 h1 = __floats2bfloat162_rn(v.z, v.w);
    float rx = v.x - __low2float(h0);
    float ry = v.y - __high2float(h0);
    float rz = v.z - __low2float(h1);
    float rw = v.w - __high2float(h1);
    __nv_bfloat162 l0 = __floats2bfloat162_rn(rx, ry);
    __nv_bfloat162 l1 = __floats2bfloat162_rn(rz, rw);
    uint2 hu = make_uint2(*(uint32_t*)&h0, *(uint32_t*)&h1);
    uint2 lu = make_uint2(*(uint32_t*)&l0, *(uint32_t*)&l1);
    *reinterpret_cast<uint2*>(hiB + off) = hu;
    *reinterpret_cast<uint2*>(loB + off) = lu;
}

// ---------------- preprocessing ----------------
__global__ void k_count(const int* __restrict__ col) {
    int e = blockIdx.x * blockDim.x + threadIdx.x;
    if (e < NEDGES) atomicAdd(&g_cnt[col[e]], 1);
}

__global__ void k_sum_dinv() {
    __shared__ int warp_sums[32];
    const int tid  = threadIdx.x;
    const int lane = tid & 31;
    const int wid  = tid >> 5;
    int i = blockIdx.x * SCAN_BLK + tid;
    int c = (i < NNODES) ? g_cnt[i] : 0;
    if (i < NNODES) g_dinv[i] = rsqrtf((float)c + 1.0f);
    int x = c;
    #pragma unroll
    for (int o = 16; o > 0; o >>= 1) x += __shfl_down_sync(0xffffffffu, x, o);
    if (lane == 0) warp_sums[wid] = x;
    __syncthreads();
    if (wid == 0) {
        int s = warp_sums[lane];
        #pragma unroll
        for (int o = 16; o > 0; o >>= 1) s += __shfl_down_sync(0xffffffffu, s, o);
        if (lane == 0) g_bsum[blockIdx.x] = s;
    }
}

__global__ void k_scan_apply() {
    __shared__ int warp_sums[32];
    __shared__ int s_base;
    const int tid  = threadIdx.x;
    const int lane = tid & 31;
    const int wid  = tid >> 5;
    const int bid  = blockIdx.x;

    if (wid == 0) {
        int v = ((lane      < bid) ? g_bsum[lane]      : 0)
              + ((lane + 32 < bid) ? g_bsum[lane + 32] : 0);
        #pragma unroll
        for (int o = 16; o > 0; o >>= 1) v += __shfl_down_sync(0xffffffffu, v, o);
        if (lane == 0) s_base = v;
    }
    if (bid == 0 && tid == 0) g_rowptr[NNODES] = NEDGES;

    int i = bid * SCAN_BLK + tid;
    int v = 0;
    if (i < NNODES) { v = g_cnt[i]; g_cnt[i] = 0; }

    int x = v;
    #pragma unroll
    for (int o = 1; o < 32; o <<= 1) {
        int y = __shfl_up_sync(0xffffffffu, x, o);
        if (lane >= o) x += y;
    }
    if (lane == 31) warp_sums[wid] = x;
    __syncthreads();
    if (wid == 0) {
        int s = warp_sums[lane];
        #pragma unroll
        for (int o = 1; o < 32; o <<= 1) {
            int y = __shfl_up_sync(0xffffffffu, s, o);
            if (lane >= o) s += y;
        }
        warp_sums[lane] = s;
    }
    __syncthreads();
    int excl = s_base + x - v + (wid > 0 ? warp_sums[wid - 1] : 0);
    if (i < NNODES) { g_rowptr[i] = excl; g_pos[i] = excl; }
}

__global__ void k_scatter(const int* __restrict__ row, const int* __restrict__ col) {
    int e = blockIdx.x * blockDim.x + threadIdx.x;
    if (e < NEDGES) {
        int c = col[e];
        int r = row[e];
        int p = atomicAdd(&g_pos[c], 1);
        g_edge[p] = make_int2(r, __float_as_int(g_dinv[r]));
    }
}

// ---------------- weight prep: W[K,N] -> W^T[N,K] tiles, hi/lo ----------------
__global__ void k_wprep(const float* __restrict__ W0, const float* __restrict__ W1,
                        const float* __restrict__ W2, const float* __restrict__ Wlin) {
    int idx = blockIdx.x * blockDim.x + threadIdx.x;
    if (idx >= 3 * 16384 + 8192) return;
    float w;
    uint32_t dst;
    if (idx < 3 * 16384) {
        int g = idx >> 14;
        int rem = idx & 16383;
        int k = rem >> 7;
        int n = rem & 127;
        const float* W = (g == 0) ? W0 : (g == 1) ? W1 : W2;
        w = W[k * 128 + n];
        dst = g * 32768 + tile_off(n, k);
    } else {
        int rem = idx - 3 * 16384;
        int k = rem >> 6;
        int n = rem & 63;
        w = Wlin[k * 64 + n];
        dst = 3 * 32768 + tile_off(n, k);
    }
    __nv_bfloat16 hi = __float2bfloat16_rn(w);
    float lo = w - __bfloat162float(hi);
    *reinterpret_cast<__nv_bfloat16*>(g_Whi + dst) = hi;
    *reinterpret_cast<__nv_bfloat16*>(g_Wlo + dst) = __float2bfloat16_rn(lo);
}

// ---------------- standalone GEMM (layer 0 only: z0 = x @ W0) ----------------
template <int NCOLS>
__global__ __launch_bounds__(256, 1)
void k_gemm_mma(const float* __restrict__ A,
                const uint4* __restrict__ Bhi4, const uint4* __restrict__ Blo4,
                const float* __restrict__ bias, float* __restrict__ C) {
    constexpr int A_BYTES = 32768;
    constexpr int B_BYTES = NCOLS * 256;
    constexpr int OFF_AHI = 0;
    constexpr int OFF_ALO = A_BYTES;
    constexpr int OFF_BHI = 2 * A_BYTES;
    constexpr int OFF_BLO = 2 * A_BYTES + B_BYTES;
    constexpr int NT8 = NCOLS / 16;
    extern __shared__ __align__(16) char smem[];

    const int tid  = threadIdx.x;
    const int wid  = tid >> 5;
    const int lane = tid & 31;
    const int tile = blockIdx.x;

    {
        char* hiB = smem + OFF_AHI;
        char* loB = smem + OFF_ALO;
        #pragma unroll
        for (int it = 0; it < 16; it++) {
            int idx = tid + it * 256;
            int r   = idx >> 5;
            int c4  = (idx & 31) * 4;
            int gr  = tile * 128 + r;
            float4 v = make_float4(0.f, 0.f, 0.f, 0.f);
            if (gr < NNODES)
                v = *reinterpret_cast<const float4*>(A + (size_t)gr * HID + c4);
            split_store(hiB, loB, tile_off(r, c4), v);
        }
        uint4* bH = reinterpret_cast<uint4*>(smem + OFF_BHI);
        uint4* bL = reinterpret_cast<uint4*>(smem + OFF_BLO);
        #pragma unroll
        for (int i = tid; i < B_BYTES / 16; i += 256) { bH[i] = Bhi4[i]; bL[i] = Blo4[i]; }
    }
    __syncthreads();

    const int wm  = wid >> 1;
    const int wn  = wid & 1;
    const int m0w = wm * 32;
    const int n0w = wn * (NCOLS / 2);

    float acc[2][NT8][4];
    #pragma unroll
    for (int mi = 0; mi < 2; mi++)
        #pragma unroll
        for (int ni = 0; ni < NT8; ni++)
            #pragma unroll
            for (int q = 0; q < 4; q++) acc[mi][ni][q] = 0.0f;

    const uint32_t sb = smem_to_u32(smem);
    const int arow    = m0w + (lane & 15);
    const int asw     = arow & 7;
    const int akc_add = lane >> 4;
    const int bn      = n0w + (lane & 7) + ((lane >> 4) << 3);
    const int bsw     = bn & 7;
    const int bkc_add = (lane >> 3) & 1;

    #pragma unroll
    for (int pass = 0; pass < 3; pass++) {
        const uint32_t Ab = sb + ((pass == 2) ? OFF_ALO : OFF_AHI);
        const uint32_t Bb = sb + ((pass == 1) ? OFF_BLO : OFF_BHI);
        #pragma unroll
        for (int s = 0; s < 8; s++) {
            const int kca = 2 * s + akc_add;
            const int kcb = 2 * s + bkc_add;
            uint32_t a[2][4];
            #pragma unroll
            for (int mi = 0; mi < 2; mi++)
                ldsm4(a[mi], Ab + (uint32_t)((arow + mi * 16) * 256 + 16 * (kca ^ asw)));
            uint32_t b[NT8][2];
            #pragma unroll
            for (int nj = 0; nj < NT8 / 2; nj++) {
                uint32_t r[4];
                ldsm4(r, Bb + (uint32_t)((bn + nj * 16) * 256 + 16 * (kcb ^ bsw)));
                b[2 * nj][0] = r[0]; b[2 * nj][1] = r[1];
                b[2 * nj + 1][0] = r[2]; b[2 * nj + 1][1] = r[3];
            }
            #pragma unroll
            for (int mi = 0; mi < 2; mi++)
                #pragma unroll
                for (int ni = 0; ni < NT8; ni++)
                    mma16816(acc[mi][ni], a[mi], b[ni]);
        }
    }

    const int rbase = tile * 128 + m0w;
    #pragma unroll
    for (int mi = 0; mi < 2; mi++) {
        int r0 = rbase + mi * 16 + (lane >> 2);
        int r1 = r0 + 8;
        #pragma unroll
        for (int ni = 0; ni < NT8; ni++) {
            int c = n0w + ni * 8 + (lane & 3) * 2;
            float bx = 0.f, by = 0.f;
            if (bias) { bx = bias[c]; by = bias[c + 1]; }
            if (r0 < NNODES) {
                float2 v = make_float2(acc[mi][ni][0] + bx, acc[mi][ni][1] + by);
                *reinterpret_cast<float2*>(C + (size_t)r0 * NCOLS + c) = v;
            }
            if (r1 < NNODES) {
                float2 v = make_float2(acc[mi][ni][2] + bx, acc[mi][ni][3] + by);
                *reinterpret_cast<float2*>(C + (size_t)r1 * NCOLS + c) = v;
            }
        }
    }
}

// ---------------- fused agg + GEMM ----------------
// in: z (fp32, prev GEMM output). per CTA (128 nodes):
//   phase 1: 32 warps aggregate 4 nodes each (gather z, norms, +bias, relu)
//            -> split hi/lo bf16 into smem ldmatrix tiles
//   phase 2: GEMM h_tile @ W -> C (+bias2)
template <int NCOLS>
__global__ __launch_bounds__(1024, 1)
void k_fused(const float* __restrict__ z,
             const float* __restrict__ bias,     // pre-GEMM (agg) bias
             const uint4* __restrict__ Bhi4, const uint4* __restrict__ Blo4,
             const float* __restrict__ bias2,    // post-GEMM bias (head)
             float* __restrict__ C) {
    constexpr int A_BYTES = 32768;
    constexpr int B_BYTES = NCOLS * 256;
    constexpr int OFF_AHI = 0;
    constexpr int OFF_ALO = A_BYTES;
    constexpr int OFF_BHI = 2 * A_BYTES;
    constexpr int OFF_BLO = 2 * A_BYTES + B_BYTES;
    extern __shared__ __align__(16) char smem[];

    const int tid  = threadIdx.x;
    const int wid  = tid >> 5;       // 0..31
    const int lane = tid & 31;
    const int tile = blockIdx.x;

    // B copy (independent of agg)
    {
        uint4* bH = reinterpret_cast<uint4*>(smem + OFF_BHI);
        uint4* bL = reinterpret_cast<uint4*>(smem + OFF_BLO);
        #pragma unroll
        for (int i = tid; i < B_BYTES / 16; i += 1024) { bH[i] = Bhi4[i]; bL[i] = Blo4[i]; }
    }

    // phase 1: aggregate 4 nodes per warp
    {
        char* hiB = smem + OFF_AHI;
        char* loB = smem + OFF_ALO;
        const size_t feat = (size_t)lane * 4;
        float4 b = *reinterpret_cast<const float4*>(bias + feat);
        #pragma unroll
        for (int it = 0; it < 4; it++) {
            const int r = wid + it * 32;            // local row 0..127
            const int n = tile * 128 + r;
            float4 acc = make_float4(0.f, 0.f, 0.f, 0.f);
            if (n < NNODES) {
                const float dn = g_dinv[n];
                float4 self = *reinterpret_cast<const float4*>(z + (size_t)n * HID + feat);
                const float sn = dn * dn;
                float4 a0 = make_float4(self.x * sn, self.y * sn, self.z * sn, self.w * sn);
                float4 a1 = make_float4(0.f, 0.f, 0.f, 0.f);
                float4 a2 = make_float4(0.f, 0.f, 0.f, 0.f);
                float4 a3 = make_float4(0.f, 0.f, 0.f, 0.f);
                const int beg = g_rowptr[n];
                const int end = g_rowptr[n + 1];
                int e = beg;
                for (; e + 4 <= end; e += 4) {
                    int2 e0 = g_edge[e],     e1 = g_edge[e + 1];
                    int2 e2 = g_edge[e + 2], e3 = g_edge[e + 3];
                    float w0 = __int_as_float(e0.y) * dn, w1 = __int_as_float(e1.y) * dn;
                    float w2 = __int_as_float(e2.y) * dn, w3 = __int_as_float(e3.y) * dn;
                    float4 v0 = *reinterpret_cast<const float4*>(z + (size_t)e0.x * HID + feat);
                    float4 v1 = *reinterpret_cast<const float4*>(z + (size_t)e1.x * HID + feat);
                    float4 v2 = *reinterpret_cast<const float4*>(z + (size_t)e2.x * HID + feat);
                    float4 v3 = *reinterpret_cast<const float4*>(z + (size_t)e3.x * HID + feat);
                    a0.x += v0.x * w0; a0.y += v0.y * w0; a0.z += v0.z * w0; a0.w += v0.w * w0;
                    a1.x += v1.x * w1; a1.y += v1.y * w1; a1.z += v1.z * w1; a1.w += v1.w * w1;
                    a2.x += v2.x * w2; a2.y += v2.y * w2; a2.z += v2.z * w2; a2.w += v2.w * w2;
                    a3.x += v3.x * w3; a3.y += v3.y * w3; a3.z += v3.z * w3; a3.w += v3.w * w3;
                }
                for (; e < end; ++e) {
                    int2 ed = g_edge[e];
                    float w = __int_as_float(ed.y) * dn;
                    float4 v = *reinterpret_cast<const float4*>(z + (size_t)ed.x * HID + feat);
                    a0.x += v.x * w; a0.y += v.y * w; a0.z += v.z * w; a0.w += v.w * w;
                }
                acc.x = fmaxf((a0.x + a1.x) + (a2.x + a3.x) + b.x, 0.0f);
                acc.y = fmaxf((a0.y + a1.y) + (a2.y + a3.y) + b.y, 0.0f);
                acc.z = fmaxf((a0.z + a1.z) + (a2.z + a3.z) + b.z, 0.0f);
                acc.w = fmaxf((a0.w + a1.w) + (a2.w + a3.w) + b.w, 0.0f);
            }
            split_store(hiB, loB, tile_off(r, lane * 4), acc);
        }
    }
    __syncthreads();

    // phase 2: GEMM. 32 warps: warp tile 16 rows x 32 cols (wm 0..7, wn 0..3)
    {
        const int wm = wid & 7;
        const int wn = wid >> 3;
        const int m0w = wm * 16;
        const int n0w = wn * (NCOLS / 4);
        constexpr int NT8 = NCOLS / 32;            // n8-tiles per warp (4 or 2)

        float acc[NT8][4];
        #pragma unroll
        for (int ni = 0; ni < NT8; ni++)
            #pragma unroll
            for (int q = 0; q < 4; q++) acc[ni][q] = 0.0f;

        const uint32_t sb = smem_to_u32(smem);
        const int arow    = m0w + (lane & 15);
        const int asw     = arow & 7;
        const int akc_add = lane >> 4;
        const int bn      = n0w + (lane & 7) + ((lane >> 4) << 3);
        const int bsw     = bn & 7;
        const int bkc_add = (lane >> 3) & 1;

        #pragma unroll
        for (int pass = 0; pass < 3; pass++) {
            const uint32_t Ab = sb + ((pass == 2) ? OFF_ALO : OFF_AHI);
            const uint32_t Bb = sb + ((pass == 1) ? OFF_BLO : OFF_BHI);
            #pragma unroll
            for (int s = 0; s < 8; s++) {
                const int kca = 2 * s + akc_add;
                const int kcb = 2 * s + bkc_add;
                uint32_t a[4];
                ldsm4(a, Ab + (uint32_t)(arow * 256 + 16 * (kca ^ asw)));
                uint32_t bfr[NT8][2];
                #pragma unroll
                for (int nj = 0; nj < NT8 / 2; nj++) {
                    uint32_t r[4];
                    ldsm4(r, Bb + (uint32_t)((bn + nj * 16) * 256 + 16 * (kcb ^ bsw)));
                    bfr[2 * nj][0] = r[0]; bfr[2 * nj][1] = r[1];
                    bfr[2 * nj + 1][0] = r[2]; bfr[2 * nj + 1][1] = r[3];
                }
                #pragma unroll
                for (int ni = 0; ni < NT8; ni++)
                    mma16816(acc[ni], a, bfr[ni]);
            }
        }

        const int r0 = tile * 128 + m0w + (lane >> 2);
        const int r1 = r0 + 8;
        #pragma unroll
        for (int ni = 0; ni < NT8; ni++) {
            int c = n0w + ni * 8 + (lane & 3) * 2;
            float bx = 0.f, by = 0.f;
            if (bias2) { bx = bias2[c]; by = bias2[c + 1]; }
            if (r0 < NNODES) {
                float2 v = make_float2(acc[ni][0] + bx, acc[ni][1] + by);
                *reinterpret_cast<float2*>(C + (size_t)r0 * NCOLS + c) = v;
            }
            if (r1 < NNODES) {
                float2 v = make_float2(acc[ni][2] + bx, acc[ni][3] + by);
                *reinterpret_cast<float2*>(C + (size_t)r1 * NCOLS + c) = v;
            }
        }
    }
}

// ---------------- launch ----------------
extern "C" void kernel_launch(void* const* d_in, const int* in_sizes, int n_in,
                              void* d_out, int out_size) {
    const float* x    = (const float*)d_in[0];
    const int*   ei   = (const int*)d_in[1];
    const int*   row  = ei;
    const int*   col  = ei + NEDGES;
    const float* W0   = (const float*)d_in[2];
    const float* b0   = (const float*)d_in[3];
    const float* W1   = (const float*)d_in[4];
    const float* b1   = (const float*)d_in[5];
    const float* W2   = (const float*)d_in[6];
    const float* b2   = (const float*)d_in[7];
    const float* Wlin = (const float*)d_in[8];
    const float* blin = (const float*)d_in[9];
    float* out = (float*)d_out;

    float *hPtr, *h2Ptr;
    cudaGetSymbolAddress((void**)&hPtr, g_h);
    cudaGetSymbolAddress((void**)&h2Ptr, g_h2);
    unsigned char *whi, *wlo;
    cudaGetSymbolAddress((void**)&whi, g_Whi);
    cudaGetSymbolAddress((void**)&wlo, g_Wlo);

    constexpr int SMEM_128 = 2 * 32768 + 2 * 32768;  // 131072
    constexpr int SMEM_64  = 2 * 32768 + 2 * 16384;  //  98304
    cudaFuncSetAttribute(k_gemm_mma<128>, cudaFuncAttributeMaxDynamicSharedMemorySize, SMEM_128);
    cudaFuncSetAttribute(k_fused<128>, cudaFuncAttributeMaxDynamicSharedMemorySize, SMEM_128);
    cudaFuncSetAttribute(k_fused<64>,  cudaFuncAttributeMaxDynamicSharedMemorySize, SMEM_64);

    static cudaStream_t s2 = nullptr;
    static cudaEvent_t evFork = nullptr, evJoin = nullptr;
    if (s2 == nullptr) {
        cudaStreamCreateWithFlags(&s2, cudaStreamNonBlocking);
        cudaEventCreateWithFlags(&evFork, cudaEventDisableTiming);
        cudaEventCreateWithFlags(&evJoin, cudaEventDisableTiming);
    }

    // fork: weight prep + layer-0 GEMM (independent of graph) on s2
    cudaEventRecord(evFork, 0);
    cudaStreamWaitEvent(s2, evFork, 0);
    k_wprep<<<(3 * 16384 + 8192 + 255) / 256, 256, 0, s2>>>(W0, W1, W2, Wlin);
    k_gemm_mma<128><<<NT, 256, SMEM_128, s2>>>(x, (const uint4*)(whi + 0 * 32768),
                                               (const uint4*)(wlo + 0 * 32768), nullptr, hPtr);
    cudaEventRecord(evJoin, s2);

    // main stream: graph preprocessing
    k_count<<<(NEDGES + 255) / 256, 256>>>(col);
    k_sum_dinv<<<NSCANBLK, SCAN_BLK>>>();
    k_scan_apply<<<NSCANBLK, SCAN_BLK>>>();
    k_scatter<<<(NEDGES + 255) / 256, 256>>>(row, col);

    // join
    cudaStreamWaitEvent(0, evJoin, 0);

    // fused layers: agg(z0)+b0+relu @ W1 -> z1 ; agg(z1)+b1+relu @ W2 -> z2 ;
    //               agg(z2)+b2+relu @ Wlin + blin -> out
    k_fused<128><<<NT, 1024, SMEM_128>>>(hPtr, b0, (const uint4*)(whi + 1 * 32768),
                                         (const uint4*)(wlo + 1 * 32768), nullptr, h2Ptr);
    k_fused<128><<<NT, 1024, SMEM_128>>>(h2Ptr, b1, (const uint4*)(whi + 2 * 32768),
                                         (const uint4*)(wlo + 2 * 32768), nullptr, hPtr);
    k_fused<64><<<NT, 1024, SMEM_64>>>(hPtr, b2, (const uint4*)(whi + 3 * 32768),
                                       (const uint4*)(wlo + 3 * 32768), blin, out);
}

// round 10
// speedup vs baseline: 1.4021x; 1.4021x over previous
#include <cuda_runtime.h>
#include <cuda_bf16.h>
#include <cstdint>

#define NNODES 50000
#define NEDGES 640000
#define HID    128
#define CLS    64
#define NT     391            // ceil(50000/128) M-tiles

#define SCAN_BLK 1024
#define NSCANBLK ((NNODES + SCAN_BLK - 1) / SCAN_BLK)   // 49

typedef unsigned long long u64;

// ---------------- scratch (static __device__, no allocation) ----------------
__device__ float g_h[NNODES * HID];                        // fp32 hidden (ping)
__device__ float g_h2[NNODES * HID];                       // fp32 hidden (pong)
__device__ __align__(16) unsigned char g_Whi[3 * 32768 + 16384]; // W^T tiles
__device__ __align__(16) unsigned char g_Wlo[3 * 32768 + 16384];
__device__ float g_dinv[NNODES];
__device__ int   g_cnt[NNODES];      // zero-initialized; invariant: zero at launch start
__device__ int   g_rowptr[NNODES + 1];
__device__ int   g_pos[NNODES];
__device__ int   g_bsum[NSCANBLK];
__device__ __align__(8) int2 g_edge[NEDGES];   // fused (srow, dinv-bits)

// ---------------- helpers ----------------
__device__ __forceinline__ uint32_t smem_to_u32(const void* p) {
    uint32_t a;
    asm("{ .reg .u64 t; cvta.to.shared.u64 t, %1; cvt.u32.u64 %0, t; }" : "=r"(a) : "l"(p));
    return a;
}

// tile layout: 128-bf16 rows (256B), 16B chunks XOR-swizzled by row for
// conflict-free ldmatrix. byte(r, k) = r*256 + 16*((k>>3) ^ (r&7)) + (k&7)*2
__device__ __forceinline__ uint32_t tile_off(int r, int k) {
    return (uint32_t)(r * 256 + 16 * (((k >> 3) ^ (r & 7))) + (k & 7) * 2);
}

__device__ __forceinline__ void ldsm4(uint32_t* r, uint32_t addr) {
    asm volatile("ldmatrix.sync.aligned.m8n8.x4.shared.b16 {%0,%1,%2,%3}, [%4];"
                 : "=r"(r[0]), "=r"(r[1]), "=r"(r[2]), "=r"(r[3]) : "r"(addr));
}
__device__ __forceinline__ void mma16816(float* c, const uint32_t* a, const uint32_t* b) {
    asm volatile("mma.sync.aligned.m16n8k16.row.col.f32.bf16.bf16.f32 "
                 "{%0,%1,%2,%3}, {%4,%5,%6,%7}, {%8,%9}, {%0,%1,%2,%3};"
                 : "+f"(c[0]), "+f"(c[1]), "+f"(c[2]), "+f"(c[3])
                 : "r"(a[0]), "r"(a[1]), "r"(a[2]), "r"(a[3]), "r"(b[0]), "r"(b[1]));
}

// split one float4 into hi/lo bf16x4 and store 8B each
__device__ __forceinline__ void split_store(char* hiB, char* loB, uint32_t off, float4 v) {
    __nv_bfloat162 h0 = __floats2bfloat162_rn(v.x, v.y);
    __nv_bfloat162 h1 = __floats2bfloat162_rn(v.z, v.w);
    float rx = v.x - __low2float(h0);
    float ry = v.y - __high2float(h0);
    float rz = v.z - __low2float(h1);
    float rw = v.w - __high2float(h1);
    __nv_bfloat162 l0 = __floats2bfloat162_rn(rx, ry);
    __nv_bfloat162 l1 = __floats2bfloat162_rn(rz, rw);
    uint2 hu = make_uint2(*(uint32_t*)&h0, *(uint32_t*)&h1);
    uint2 lu = make_uint2(*(uint32_t*)&l0, *(uint32_t*)&l1);
    *reinterpret_cast<uint2*>(hiB + off) = hu;
    *reinterpret_cast<uint2*>(loB + off) = lu;
}

// ---------------- preprocessing ----------------
// 2 edges per thread (int2 loads)
__global__ void k_count(const int2* __restrict__ col2) {
    int i = blockIdx.x * blockDim.x + threadIdx.x;
    if (i < NEDGES / 2) {
        int2 c = col2[i];
        atomicAdd(&g_cnt[c.x], 1);
        atomicAdd(&g_cnt[c.y], 1);
    }
}

// per-block sum of cnt + dinv computation
__global__ void k_sum_dinv() {
    __shared__ int warp_sums[32];
    const int tid  = threadIdx.x;
    const int lane = tid & 31;
    const int wid  = tid >> 5;
    int i = blockIdx.x * SCAN_BLK + tid;
    int c = (i < NNODES) ? g_cnt[i] : 0;
    if (i < NNODES) g_dinv[i] = rsqrtf((float)c + 1.0f);
    int x = c;
    #pragma unroll
    for (int o = 16; o > 0; o >>= 1) x += __shfl_down_sync(0xffffffffu, x, o);
    if (lane == 0) warp_sums[wid] = x;
    __syncthreads();
    if (wid == 0) {
        int s = warp_sums[lane];
        #pragma unroll
        for (int o = 16; o > 0; o >>= 1) s += __shfl_down_sync(0xffffffffu, s, o);
        if (lane == 0) g_bsum[blockIdx.x] = s;
    }
}

// per-block scan + inline block-prefix of g_bsum -> rowptr/pos; clears g_cnt
__global__ void k_scan_apply() {
    __shared__ int warp_sums[32];
    __shared__ int s_base;
    const int tid  = threadIdx.x;
    const int lane = tid & 31;
    const int wid  = tid >> 5;
    const int bid  = blockIdx.x;

    if (wid == 0) {
        int v = ((lane      < bid) ? g_bsum[lane]      : 0)
              + ((lane + 32 < bid) ? g_bsum[lane + 32] : 0);
        #pragma unroll
        for (int o = 16; o > 0; o >>= 1) v += __shfl_down_sync(0xffffffffu, v, o);
        if (lane == 0) s_base = v;
    }
    if (bid == 0 && tid == 0) g_rowptr[NNODES] = NEDGES;

    int i = bid * SCAN_BLK + tid;
    int v = 0;
    if (i < NNODES) { v = g_cnt[i]; g_cnt[i] = 0; }   // read + restore invariant

    int x = v;
    #pragma unroll
    for (int o = 1; o < 32; o <<= 1) {
        int y = __shfl_up_sync(0xffffffffu, x, o);
        if (lane >= o) x += y;
    }
    if (lane == 31) warp_sums[wid] = x;
    __syncthreads();
    if (wid == 0) {
        int s = warp_sums[lane];
        #pragma unroll
        for (int o = 1; o < 32; o <<= 1) {
            int y = __shfl_up_sync(0xffffffffu, s, o);
            if (lane >= o) s += y;
        }
        warp_sums[lane] = s;
    }
    __syncthreads();
    int excl = s_base + x - v + (wid > 0 ? warp_sums[wid - 1] : 0);
    if (i < NNODES) { g_rowptr[i] = excl; g_pos[i] = excl; }
}

// 2 edges per thread (int2 loads)
__global__ void k_scatter(const int2* __restrict__ row2, const int2* __restrict__ col2) {
    int i = blockIdx.x * blockDim.x + threadIdx.x;
    if (i < NEDGES / 2) {
        int2 c = col2[i];
        int2 r = row2[i];
        int p0 = atomicAdd(&g_pos[c.x], 1);
        g_edge[p0] = make_int2(r.x, __float_as_int(g_dinv[r.x]));
        int p1 = atomicAdd(&g_pos[c.y], 1);
        g_edge[p1] = make_int2(r.y, __float_as_int(g_dinv[r.y]));
    }
}

// ---------------- weight prep: W[K,N] -> W^T[N,K] tiles, hi/lo ----------------
__global__ void k_wprep(const float* __restrict__ W0, const float* __restrict__ W1,
                        const float* __restrict__ W2, const float* __restrict__ Wlin) {
    int idx = blockIdx.x * blockDim.x + threadIdx.x;
    if (idx >= 3 * 16384 + 8192) return;
    float w;
    uint32_t dst;
    if (idx < 3 * 16384) {
        int g = idx >> 14;
        int rem = idx & 16383;
        int k = rem >> 7;
        int n = rem & 127;
        const float* W = (g == 0) ? W0 : (g == 1) ? W1 : W2;
        w = W[k * 128 + n];
        dst = g * 32768 + tile_off(n, k);
    } else {
        int rem = idx - 3 * 16384;
        int k = rem >> 6;
        int n = rem & 63;
        w = Wlin[k * 64 + n];
        dst = 3 * 32768 + tile_off(n, k);
    }
    __nv_bfloat16 hi = __float2bfloat16_rn(w);
    float lo = w - __bfloat162float(hi);
    *reinterpret_cast<__nv_bfloat16*>(g_Whi + dst) = hi;
    *reinterpret_cast<__nv_bfloat16*>(g_Wlo + dst) = __float2bfloat16_rn(lo);
}

// ---------------- tensor-core GEMM via mma.sync, split-bf16 x3 passes ----------
// C[M, NCOLS] = A[M,128] @ W[128,NCOLS]; A fp32, split hi/lo into smem on load.
// 256 threads, warp tile 32 x NCOLS/2.
template <int NCOLS>
__global__ __launch_bounds__(256, 1)
void k_gemm_mma(const float* __restrict__ A,
                const uint4* __restrict__ Bhi4, const uint4* __restrict__ Blo4,
                const float* __restrict__ bias, float* __restrict__ C) {
    constexpr int A_BYTES = 32768;
    constexpr int B_BYTES = NCOLS * 256;
    constexpr int OFF_AHI = 0;
    constexpr int OFF_ALO = A_BYTES;
    constexpr int OFF_BHI = 2 * A_BYTES;
    constexpr int OFF_BLO = 2 * A_BYTES + B_BYTES;
    constexpr int NT8 = NCOLS / 16;
    extern __shared__ __align__(16) char smem[];

    const int tid  = threadIdx.x;
    const int wid  = tid >> 5;
    const int lane = tid & 31;
    const int tile = blockIdx.x;

    {
        char* hiB = smem + OFF_AHI;
        char* loB = smem + OFF_ALO;
        #pragma unroll
        for (int it = 0; it < 16; it++) {
            int idx = tid + it * 256;
            int r   = idx >> 5;
            int c4  = (idx & 31) * 4;
            int gr  = tile * 128 + r;
            float4 v = make_float4(0.f, 0.f, 0.f, 0.f);
            if (gr < NNODES)
                v = *reinterpret_cast<const float4*>(A + (size_t)gr * HID + c4);
            split_store(hiB, loB, tile_off(r, c4), v);
        }
        uint4* bH = reinterpret_cast<uint4*>(smem + OFF_BHI);
        uint4* bL = reinterpret_cast<uint4*>(smem + OFF_BLO);
        #pragma unroll
        for (int i = tid; i < B_BYTES / 16; i += 256) { bH[i] = Bhi4[i]; bL[i] = Blo4[i]; }
    }
    __syncthreads();

    const int wm  = wid >> 1;
    const int wn  = wid & 1;
    const int m0w = wm * 32;
    const int n0w = wn * (NCOLS / 2);

    float acc[2][NT8][4];
    #pragma unroll
    for (int mi = 0; mi < 2; mi++)
        #pragma unroll
        for (int ni = 0; ni < NT8; ni++)
            #pragma unroll
            for (int q = 0; q < 4; q++) acc[mi][ni][q] = 0.0f;

    const uint32_t sb = smem_to_u32(smem);
    const int arow    = m0w + (lane & 15);
    const int asw     = arow & 7;
    const int akc_add = lane >> 4;
    const int bn      = n0w + (lane & 7) + ((lane >> 4) << 3);
    const int bsw     = bn & 7;
    const int bkc_add = (lane >> 3) & 1;

    #pragma unroll
    for (int pass = 0; pass < 3; pass++) {
        const uint32_t Ab = sb + ((pass == 2) ? OFF_ALO : OFF_AHI);
        const uint32_t Bb = sb + ((pass == 1) ? OFF_BLO : OFF_BHI);
        #pragma unroll
        for (int s = 0; s < 8; s++) {
            const int kca = 2 * s + akc_add;
            const int kcb = 2 * s + bkc_add;
            uint32_t a[2][4];
            #pragma unroll
            for (int mi = 0; mi < 2; mi++)
                ldsm4(a[mi], Ab + (uint32_t)((arow + mi * 16) * 256 + 16 * (kca ^ asw)));
            uint32_t b[NT8][2];
            #pragma unroll
            for (int nj = 0; nj < NT8 / 2; nj++) {
                uint32_t r[4];
                ldsm4(r, Bb + (uint32_t)((bn + nj * 16) * 256 + 16 * (kcb ^ bsw)));
                b[2 * nj][0] = r[0]; b[2 * nj][1] = r[1];
                b[2 * nj + 1][0] = r[2]; b[2 * nj + 1][1] = r[3];
            }
            #pragma unroll
            for (int mi = 0; mi < 2; mi++)
                #pragma unroll
                for (int ni = 0; ni < NT8; ni++)
                    mma16816(acc[mi][ni], a[mi], b[ni]);
        }
    }

    const int rbase = tile * 128 + m0w;
    #pragma unroll
    for (int mi = 0; mi < 2; mi++) {
        int r0 = rbase + mi * 16 + (lane >> 2);
        int r1 = r0 + 8;
        #pragma unroll
        for (int ni = 0; ni < NT8; ni++) {
            int c = n0w + ni * 8 + (lane & 3) * 2;
            float bx = 0.f, by = 0.f;
            if (bias) { bx = bias[c]; by = bias[c + 1]; }
            if (r0 < NNODES) {
                float2 v = make_float2(acc[mi][ni][0] + bx, acc[mi][ni][1] + by);
                *reinterpret_cast<float2*>(C + (size_t)r0 * NCOLS + c) = v;
            }
            if (r1 < NNODES) {
                float2 v = make_float2(acc[mi][ni][2] + bx, acc[mi][ni][3] + by);
                *reinterpret_cast<float2*>(C + (size_t)r1 * NCOLS + c) = v;
            }
        }
    }
}

// ---------------- aggregation (4-way edge ILP): fp32 in, fp32 out ----------------
__global__ void k_agg(const float* __restrict__ h,
                      const float* __restrict__ bias,
                      float* __restrict__ out) {
    int gwarp = (blockIdx.x * blockDim.x + threadIdx.x) >> 5;
    int lane  = threadIdx.x & 31;
    if (gwarp >= NNODES) return;
    const int n = gwarp;

    const float dn = g_dinv[n];
    const size_t feat = (size_t)lane * 4;

    float4 self = *reinterpret_cast<const float4*>(h + (size_t)n * HID + feat);
    const float sn = dn * dn;
    float4 acc0 = make_float4(self.x * sn, self.y * sn, self.z * sn, self.w * sn);
    float4 acc1 = make_float4(0.f, 0.f, 0.f, 0.f);
    float4 acc2 = make_float4(0.f, 0.f, 0.f, 0.f);
    float4 acc3 = make_float4(0.f, 0.f, 0.f, 0.f);

    const int beg = g_rowptr[n];
    const int end = g_rowptr[n + 1];

    int e = beg;
    for (; e + 4 <= end; e += 4) {
        int2 e0 = g_edge[e],     e1 = g_edge[e + 1];
        int2 e2 = g_edge[e + 2], e3 = g_edge[e + 3];
        float w0 = __int_as_float(e0.y) * dn, w1 = __int_as_float(e1.y) * dn;
        float w2 = __int_as_float(e2.y) * dn, w3 = __int_as_float(e3.y) * dn;
        float4 v0 = *reinterpret_cast<const float4*>(h + (size_t)e0.x * HID + feat);
        float4 v1 = *reinterpret_cast<const float4*>(h + (size_t)e1.x * HID + feat);
        float4 v2 = *reinterpret_cast<const float4*>(h + (size_t)e2.x * HID + feat);
        float4 v3 = *reinterpret_cast<const float4*>(h + (size_t)e3.x * HID + feat);
        acc0.x += v0.x * w0; acc0.y += v0.y * w0; acc0.z += v0.z * w0; acc0.w += v0.w * w0;
        acc1.x += v1.x * w1; acc1.y += v1.y * w1; acc1.z += v1.z * w1; acc1.w += v1.w * w1;
        acc2.x += v2.x * w2; acc2.y += v2.y * w2; acc2.z += v2.z * w2; acc2.w += v2.w * w2;
        acc3.x += v3.x * w3; acc3.y += v3.y * w3; acc3.z += v3.z * w3; acc3.w += v3.w * w3;
    }
    for (; e < end; ++e) {
        int2 ed = g_edge[e];
        float w = __int_as_float(ed.y) * dn;
        float4 v = *reinterpret_cast<const float4*>(h + (size_t)ed.x * HID + feat);
        acc0.x += v.x * w; acc0.y += v.y * w; acc0.z += v.z * w; acc0.w += v.w * w;
    }

    float4 acc;
    acc.x = (acc0.x + acc1.x) + (acc2.x + acc3.x);
    acc.y = (acc0.y + acc1.y) + (acc2.y + acc3.y);
    acc.z = (acc0.z + acc1.z) + (acc2.z + acc3.z);
    acc.w = (acc0.w + acc1.w) + (acc2.w + acc3.w);

    float4 b = *reinterpret_cast<const float4*>(bias + feat);
    acc.x = fmaxf(acc.x + b.x, 0.0f);
    acc.y = fmaxf(acc.y + b.y, 0.0f);
    acc.z = fmaxf(acc.z + b.z, 0.0f);
    acc.w = fmaxf(acc.w + b.w, 0.0f);

    *reinterpret_cast<float4*>(out + (size_t)n * HID + feat) = acc;
}

// ---------------- launch ----------------
extern "C" void kernel_launch(void* const* d_in, const int* in_sizes, int n_in,
                              void* d_out, int out_size) {
    const float* x    = (const float*)d_in[0];
    const int*   ei   = (const int*)d_in[1];
    const int*   row  = ei;
    const int*   col  = ei + NEDGES;
    const float* W0   = (const float*)d_in[2];
    const float* b0   = (const float*)d_in[3];
    const float* W1   = (const float*)d_in[4];
    const float* b1   = (const float*)d_in[5];
    const float* W2   = (const float*)d_in[6];
    const float* b2   = (const float*)d_in[7];
    const float* Wlin = (const float*)d_in[8];
    const float* blin = (const float*)d_in[9];
    float* out = (float*)d_out;

    float *hPtr, *h2Ptr;
    cudaGetSymbolAddress((void**)&hPtr, g_h);
    cudaGetSymbolAddress((void**)&h2Ptr, g_h2);
    unsigned char *whi, *wlo;
    cudaGetSymbolAddress((void**)&whi, g_Whi);
    cudaGetSymbolAddress((void**)&wlo, g_Wlo);

    constexpr int SMEM_128 = 2 * 32768 + 2 * 32768;  // 131072
    constexpr int SMEM_64  = 2 * 32768 + 2 * 16384;  //  98304
    cudaFuncSetAttribute(k_gemm_mma<128>, cudaFuncAttributeMaxDynamicSharedMemorySize, SMEM_128);
    cudaFuncSetAttribute(k_gemm_mma<64>,  cudaFuncAttributeMaxDynamicSharedMemorySize, SMEM_64);

    // one-time side-stream + events (handles only; no device memory)
    static cudaStream_t s2 = nullptr;
    static cudaEvent_t evFork = nullptr, evJoin = nullptr;
    if (s2 == nullptr) {
        cudaStreamCreateWithFlags(&s2, cudaStreamNonBlocking);
        cudaEventCreateWithFlags(&evFork, cudaEventDisableTiming);
        cudaEventCreateWithFlags(&evJoin, cudaEventDisableTiming);
    }

    // fork: weight prep + layer-0 GEMM (independent of graph) on s2
    cudaEventRecord(evFork, 0);
    cudaStreamWaitEvent(s2, evFork, 0);
    k_wprep<<<(3 * 16384 + 8192 + 255) / 256, 256, 0, s2>>>(W0, W1, W2, Wlin);
    k_gemm_mma<128><<<NT, 256, SMEM_128, s2>>>(x, (const uint4*)(whi + 0 * 32768),
                                               (const uint4*)(wlo + 0 * 32768), nullptr, hPtr);
    cudaEventRecord(evJoin, s2);

    // main stream: graph preprocessing (g_cnt zero-invariant kept by k_scan_apply)
    k_count<<<(NEDGES / 2 + 255) / 256, 256>>>((const int2*)col);
    k_sum_dinv<<<NSCANBLK, SCAN_BLK>>>();
    k_scan_apply<<<NSCANBLK, SCAN_BLK>>>();
    k_scatter<<<(NEDGES / 2 + 255) / 256, 256>>>((const int2*)row, (const int2*)col);

    // join
    cudaStreamWaitEvent(0, evJoin, 0);

    const int agg_blocks = (NNODES * 32 + 255) / 256;

    k_agg<<<agg_blocks, 256>>>(hPtr, b0, h2Ptr);
    // layer 1
    k_gemm_mma<128><<<NT, 256, SMEM_128>>>(h2Ptr, (const uint4*)(whi + 1 * 32768),
                                           (const uint4*)(wlo + 1 * 32768), nullptr, hPtr);
    k_agg<<<agg_blocks, 256>>>(hPtr, b1, h2Ptr);
    // layer 2
    k_gemm_mma<128><<<NT, 256, SMEM_128>>>(h2Ptr, (const uint4*)(whi + 2 * 32768),
                                           (const uint4*)(wlo + 2 * 32768), nullptr, hPtr);
    k_agg<<<agg_blocks, 256>>>(hPtr, b2, h2Ptr);
    // head
    k_gemm_mma<64><<<NT, 256, SMEM_64>>>(h2Ptr, (const uint4*)(whi + 3 * 32768),
                                         (const uint4*)(wlo + 3 * 32768), blin, out);
}

// round 11
// speedup vs baseline: 1.4267x; 1.0176x over previous
#include <cuda_runtime.h>
#include <cuda_bf16.h>
#include <cstdint>

#define NNODES 50000
#define NEDGES 640000
#define HID    128
#define CLS    64
#define NT     391            // ceil(50000/128) M-tiles

#define SCAN_BLK 1024
#define NSCANBLK ((NNODES + SCAN_BLK - 1) / SCAN_BLK)   // 49

typedef unsigned long long u64;

// ---------------- scratch (static __device__, no allocation) ----------------
__device__ float g_h[NNODES * HID];                        // fp32 hidden (ping)
__device__ float g_h2[NNODES * HID];                       // fp32 hidden (pong)
__device__ __align__(16) unsigned char g_Whi[3 * 32768 + 16384]; // W^T tiles
__device__ __align__(16) unsigned char g_Wlo[3 * 32768 + 16384];
__device__ float g_dinv[NNODES];
__device__ int   g_cnt[NNODES];      // zero-initialized; invariant: zero at launch start
__device__ int   g_rowptr[NNODES + 1];
__device__ int   g_pos[NNODES];
__device__ __align__(8) int2 g_edge[NEDGES];   // fused (srow, dinv-bits)

// ---------------- helpers ----------------
__device__ __forceinline__ uint32_t smem_to_u32(const void* p) {
    uint32_t a;
    asm("{ .reg .u64 t; cvta.to.shared.u64 t, %1; cvt.u32.u64 %0, t; }" : "=r"(a) : "l"(p));
    return a;
}

// tile layout: 128-bf16 rows (256B), 16B chunks XOR-swizzled by row for
// conflict-free ldmatrix. byte(r, k) = r*256 + 16*((k>>3) ^ (r&7)) + (k&7)*2
__device__ __forceinline__ uint32_t tile_off(int r, int k) {
    return (uint32_t)(r * 256 + 16 * (((k >> 3) ^ (r & 7))) + (k & 7) * 2);
}

__device__ __forceinline__ void ldsm4(uint32_t* r, uint32_t addr) {
    asm volatile("ldmatrix.sync.aligned.m8n8.x4.shared.b16 {%0,%1,%2,%3}, [%4];"
                 : "=r"(r[0]), "=r"(r[1]), "=r"(r[2]), "=r"(r[3]) : "r"(addr));
}
__device__ __forceinline__ void mma16816(float* c, const uint32_t* a, const uint32_t* b) {
    asm volatile("mma.sync.aligned.m16n8k16.row.col.f32.bf16.bf16.f32 "
                 "{%0,%1,%2,%3}, {%4,%5,%6,%7}, {%8,%9}, {%0,%1,%2,%3};"
                 : "+f"(c[0]), "+f"(c[1]), "+f"(c[2]), "+f"(c[3])
                 : "r"(a[0]), "r"(a[1]), "r"(a[2]), "r"(a[3]), "r"(b[0]), "r"(b[1]));
}

// split one float4 into hi/lo bf16x4 and store 8B each
__device__ __forceinline__ void split_store(char* hiB, char* loB, uint32_t off, float4 v) {
    __nv_bfloat162 h0 = __floats2bfloat162_rn(v.x, v.y);
    __nv_bfloat162 h1 = __floats2bfloat162_rn(v.z, v.w);
    float rx = v.x - __low2float(h0);
    float ry = v.y - __high2float(h0);
    float rz = v.z - __low2float(h1);
    float rw = v.w - __high2float(h1);
    __nv_bfloat162 l0 = __floats2bfloat162_rn(rx, ry);
    __nv_bfloat162 l1 = __floats2bfloat162_rn(rz, rw);
    uint2 hu = make_uint2(*(uint32_t*)&h0, *(uint32_t*)&h1);
    uint2 lu = make_uint2(*(uint32_t*)&l0, *(uint32_t*)&l1);
    *reinterpret_cast<uint2*>(hiB + off) = hu;
    *reinterpret_cast<uint2*>(loB + off) = lu;
}

// ---------------- preprocessing ----------------
__global__ void k_count(const int* __restrict__ col) {
    int e = blockIdx.x * blockDim.x + threadIdx.x;
    if (e < NEDGES) atomicAdd(&g_cnt[col[e]], 1);
}

// fused: per-block prefix base (direct sum of preceding counts) + dinv + scan
// -> rowptr/pos. g_cnt NOT cleared here (cross-block race); cleared in k_agg.
__global__ void k_scan_fused() {
    __shared__ int warp_sums[32];
    __shared__ int s_base;
    const int tid  = threadIdx.x;
    const int lane = tid & 31;
    const int wid  = tid >> 5;
    const int bid  = blockIdx.x;

    // phase A: s_base = sum(g_cnt[0 .. bid*SCAN_BLK))
    int pre = 0;
    const int lim = bid * SCAN_BLK;
    for (int j = tid; j < lim; j += SCAN_BLK) pre += g_cnt[j];
    #pragma unroll
    for (int o = 16; o > 0; o >>= 1) pre += __shfl_down_sync(0xffffffffu, pre, o);
    if (lane == 0) warp_sums[wid] = pre;
    __syncthreads();
    if (wid == 0) {
        int s = warp_sums[lane];
        #pragma unroll
        for (int o = 16; o > 0; o >>= 1) s += __shfl_down_sync(0xffffffffu, s, o);
        if (lane == 0) s_base = s;
    }
    __syncthreads();

    if (bid == 0 && tid == 0) g_rowptr[NNODES] = NEDGES;

    // phase B: dinv + per-block exclusive scan
    int i = bid * SCAN_BLK + tid;
    int v = 0;
    if (i < NNODES) {
        v = g_cnt[i];
        g_dinv[i] = rsqrtf((float)v + 1.0f);
    }
    int x = v;
    #pragma unroll
    for (int o = 1; o < 32; o <<= 1) {
        int y = __shfl_up_sync(0xffffffffu, x, o);
        if (lane >= o) x += y;
    }
    if (lane == 31) warp_sums[wid] = x;
    __syncthreads();
    if (wid == 0) {
        int s = warp_sums[lane];
        #pragma unroll
        for (int o = 1; o < 32; o <<= 1) {
            int y = __shfl_up_sync(0xffffffffu, s, o);
            if (lane >= o) s += y;
        }
        warp_sums[lane] = s;
    }
    __syncthreads();
    int excl = s_base + x - v + (wid > 0 ? warp_sums[wid - 1] : 0);
    if (i < NNODES) { g_rowptr[i] = excl; g_pos[i] = excl; }
}

__global__ void k_scatter(const int* __restrict__ row, const int* __restrict__ col) {
    int e = blockIdx.x * blockDim.x + threadIdx.x;
    if (e < NEDGES) {
        int c = col[e];
        int r = row[e];
        int p = atomicAdd(&g_pos[c], 1);
        g_edge[p] = make_int2(r, __float_as_int(g_dinv[r]));
    }
}

// ---------------- weight prep: W[K,N] -> W^T[N,K] tiles, hi/lo ----------------
__global__ void k_wprep(const float* __restrict__ W0, const float* __restrict__ W1,
                        const float* __restrict__ W2, const float* __restrict__ Wlin) {
    int idx = blockIdx.x * blockDim.x + threadIdx.x;
    if (idx >= 3 * 16384 + 8192) return;
    float w;
    uint32_t dst;
    if (idx < 3 * 16384) {
        int g = idx >> 14;
        int rem = idx & 16383;
        int k = rem >> 7;
        int n = rem & 127;
        const float* W = (g == 0) ? W0 : (g == 1) ? W1 : W2;
        w = W[k * 128 + n];
        dst = g * 32768 + tile_off(n, k);
    } else {
        int rem = idx - 3 * 16384;
        int k = rem >> 6;
        int n = rem & 63;
        w = Wlin[k * 64 + n];
        dst = 3 * 32768 + tile_off(n, k);
    }
    __nv_bfloat16 hi = __float2bfloat16_rn(w);
    float lo = w - __bfloat162float(hi);
    *reinterpret_cast<__nv_bfloat16*>(g_Whi + dst) = hi;
    *reinterpret_cast<__nv_bfloat16*>(g_Wlo + dst) = __float2bfloat16_rn(lo);
}

// ---------------- tensor-core GEMM via mma.sync, split-bf16 x3 passes ----------
// C[M, NCOLS] = A[M,128] @ W[128,NCOLS]; A fp32, split hi/lo into smem on load.
// 256 threads, warp tile 32 x NCOLS/2.
template <int NCOLS>
__global__ __launch_bounds__(256, 1)
void k_gemm_mma(const float* __restrict__ A,
                const uint4* __restrict__ Bhi4, const uint4* __restrict__ Blo4,
                const float* __restrict__ bias, float* __restrict__ C) {
    constexpr int A_BYTES = 32768;
    constexpr int B_BYTES = NCOLS * 256;
    constexpr int OFF_AHI = 0;
    constexpr int OFF_ALO = A_BYTES;
    constexpr int OFF_BHI = 2 * A_BYTES;
    constexpr int OFF_BLO = 2 * A_BYTES + B_BYTES;
    constexpr int NT8 = NCOLS / 16;
    extern __shared__ __align__(16) char smem[];

    const int tid  = threadIdx.x;
    const int wid  = tid >> 5;
    const int lane = tid & 31;
    const int tile = blockIdx.x;

    {
        char* hiB = smem + OFF_AHI;
        char* loB = smem + OFF_ALO;
        #pragma unroll
        for (int it = 0; it < 16; it++) {
            int idx = tid + it * 256;
            int r   = idx >> 5;
            int c4  = (idx & 31) * 4;
            int gr  = tile * 128 + r;
            float4 v = make_float4(0.f, 0.f, 0.f, 0.f);
            if (gr < NNODES)
                v = *reinterpret_cast<const float4*>(A + (size_t)gr * HID + c4);
            split_store(hiB, loB, tile_off(r, c4), v);
        }
        uint4* bH = reinterpret_cast<uint4*>(smem + OFF_BHI);
        uint4* bL = reinterpret_cast<uint4*>(smem + OFF_BLO);
        #pragma unroll
        for (int i = tid; i < B_BYTES / 16; i += 256) { bH[i] = Bhi4[i]; bL[i] = Blo4[i]; }
    }
    __syncthreads();

    const int wm  = wid >> 1;
    const int wn  = wid & 1;
    const int m0w = wm * 32;
    const int n0w = wn * (NCOLS / 2);

    float acc[2][NT8][4];
    #pragma unroll
    for (int mi = 0; mi < 2; mi++)
        #pragma unroll
        for (int ni = 0; ni < NT8; ni++)
            #pragma unroll
            for (int q = 0; q < 4; q++) acc[mi][ni][q] = 0.0f;

    const uint32_t sb = smem_to_u32(smem);
    const int arow    = m0w + (lane & 15);
    const int asw     = arow & 7;
    const int akc_add = lane >> 4;
    const int bn      = n0w + (lane & 7) + ((lane >> 4) << 3);
    const int bsw     = bn & 7;
    const int bkc_add = (lane >> 3) & 1;

    #pragma unroll
    for (int pass = 0; pass < 3; pass++) {
        const uint32_t Ab = sb + ((pass == 2) ? OFF_ALO : OFF_AHI);
        const uint32_t Bb = sb + ((pass == 1) ? OFF_BLO : OFF_BHI);
        #pragma unroll
        for (int s = 0; s < 8; s++) {
            const int kca = 2 * s + akc_add;
            const int kcb = 2 * s + bkc_add;
            uint32_t a[2][4];
            #pragma unroll
            for (int mi = 0; mi < 2; mi++)
                ldsm4(a[mi], Ab + (uint32_t)((arow + mi * 16) * 256 + 16 * (kca ^ asw)));
            uint32_t b[NT8][2];
            #pragma unroll
            for (int nj = 0; nj < NT8 / 2; nj++) {
                uint32_t r[4];
                ldsm4(r, Bb + (uint32_t)((bn + nj * 16) * 256 + 16 * (kcb ^ bsw)));
                b[2 * nj][0] = r[0]; b[2 * nj][1] = r[1];
                b[2 * nj + 1][0] = r[2]; b[2 * nj + 1][1] = r[3];
            }
            #pragma unroll
            for (int mi = 0; mi < 2; mi++)
                #pragma unroll
                for (int ni = 0; ni < NT8; ni++)
                    mma16816(acc[mi][ni], a[mi], b[ni]);
        }
    }

    const int rbase = tile * 128 + m0w;
    #pragma unroll
    for (int mi = 0; mi < 2; mi++) {
        int r0 = rbase + mi * 16 + (lane >> 2);
        int r1 = r0 + 8;
        #pragma unroll
        for (int ni = 0; ni < NT8; ni++) {
            int c = n0w + ni * 8 + (lane & 3) * 2;
            float bx = 0.f, by = 0.f;
            if (bias) { bx = bias[c]; by = bias[c + 1]; }
            if (r0 < NNODES) {
                float2 v = make_float2(acc[mi][ni][0] + bx, acc[mi][ni][1] + by);
                *reinterpret_cast<float2*>(C + (size_t)r0 * NCOLS + c) = v;
            }
            if (r1 < NNODES) {
                float2 v = make_float2(acc[mi][ni][2] + bx, acc[mi][ni][3] + by);
                *reinterpret_cast<float2*>(C + (size_t)r1 * NCOLS + c) = v;
            }
        }
    }
}

// ---------------- aggregation (4-way edge ILP): fp32 in, fp32 out ----------------
// also restores the g_cnt == 0 invariant for the next launch replay
__global__ void k_agg(const float* __restrict__ h,
                      const float* __restrict__ bias,
                      float* __restrict__ out) {
    int gwarp = (blockIdx.x * blockDim.x + threadIdx.x) >> 5;
    int lane  = threadIdx.x & 31;
    if (gwarp >= NNODES) return;
    const int n = gwarp;
    if (lane == 0) g_cnt[n] = 0;     // maintain zero-invariant (idempotent)

    const float dn = g_dinv[n];
    const size_t feat = (size_t)lane * 4;

    float4 self = *reinterpret_cast<const float4*>(h + (size_t)n * HID + feat);
    const float sn = dn * dn;
    float4 acc0 = make_float4(self.x * sn, self.y * sn, self.z * sn, self.w * sn);
    float4 acc1 = make_float4(0.f, 0.f, 0.f, 0.f);
    float4 acc2 = make_float4(0.f, 0.f, 0.f, 0.f);
    float4 acc3 = make_float4(0.f, 0.f, 0.f, 0.f);

    const int beg = g_rowptr[n];
    const int end = g_rowptr[n + 1];

    int e = beg;
    for (; e + 4 <= end; e += 4) {
        int2 e0 = g_edge[e],     e1 = g_edge[e + 1];
        int2 e2 = g_edge[e + 2], e3 = g_edge[e + 3];
        float w0 = __int_as_float(e0.y) * dn, w1 = __int_as_float(e1.y) * dn;
        float w2 = __int_as_float(e2.y) * dn, w3 = __int_as_float(e3.y) * dn;
        float4 v0 = *reinterpret_cast<const float4*>(h + (size_t)e0.x * HID + feat);
        float4 v1 = *reinterpret_cast<const float4*>(h + (size_t)e1.x * HID + feat);
        float4 v2 = *reinterpret_cast<const float4*>(h + (size_t)e2.x * HID + feat);
        float4 v3 = *reinterpret_cast<const float4*>(h + (size_t)e3.x * HID + feat);
        acc0.x += v0.x * w0; acc0.y += v0.y * w0; acc0.z += v0.z * w0; acc0.w += v0.w * w0;
        acc1.x += v1.x * w1; acc1.y += v1.y * w1; acc1.z += v1.z * w1; acc1.w += v1.w * w1;
        acc2.x += v2.x * w2; acc2.y += v2.y * w2; acc2.z += v2.z * w2; acc2.w += v2.w * w2;
        acc3.x += v3.x * w3; acc3.y += v3.y * w3; acc3.z += v3.z * w3; acc3.w += v3.w * w3;
    }
    for (; e < end; ++e) {
        int2 ed = g_edge[e];
        float w = __int_as_float(ed.y) * dn;
        float4 v = *reinterpret_cast<const float4*>(h + (size_t)ed.x * HID + feat);
        acc0.x += v.x * w; acc0.y += v.y * w; acc0.z += v.z * w; acc0.w += v.w * w;
    }

    float4 acc;
    acc.x = (acc0.x + acc1.x) + (acc2.x + acc3.x);
    acc.y = (acc0.y + acc1.y) + (acc2.y + acc3.y);
    acc.z = (acc0.z + acc1.z) + (acc2.z + acc3.z);
    acc.w = (acc0.w + acc1.w) + (acc2.w + acc3.w);

    float4 b = *reinterpret_cast<const float4*>(bias + feat);
    acc.x = fmaxf(acc.x + b.x, 0.0f);
    acc.y = fmaxf(acc.y + b.y, 0.0f);
    acc.z = fmaxf(acc.z + b.z, 0.0f);
    acc.w = fmaxf(acc.w + b.w, 0.0f);

    *reinterpret_cast<float4*>(out + (size_t)n * HID + feat) = acc;
}

// ---------------- launch ----------------
extern "C" void kernel_launch(void* const* d_in, const int* in_sizes, int n_in,
                              void* d_out, int out_size) {
    const float* x    = (const float*)d_in[0];
    const int*   ei   = (const int*)d_in[1];
    const int*   row  = ei;
    const int*   col  = ei + NEDGES;
    const float* W0   = (const float*)d_in[2];
    const float* b0   = (const float*)d_in[3];
    const float* W1   = (const float*)d_in[4];
    const float* b1   = (const float*)d_in[5];
    const float* W2   = (const float*)d_in[6];
    const float* b2   = (const float*)d_in[7];
    const float* Wlin = (const float*)d_in[8];
    const float* blin = (const float*)d_in[9];
    float* out = (float*)d_out;

    float *hPtr, *h2Ptr;
    cudaGetSymbolAddress((void**)&hPtr, g_h);
    cudaGetSymbolAddress((void**)&h2Ptr, g_h2);
    unsigned char *whi, *wlo;
    cudaGetSymbolAddress((void**)&whi, g_Whi);
    cudaGetSymbolAddress((void**)&wlo, g_Wlo);

    constexpr int SMEM_128 = 2 * 32768 + 2 * 32768;  // 131072
    constexpr int SMEM_64  = 2 * 32768 + 2 * 16384;  //  98304
    cudaFuncSetAttribute(k_gemm_mma<128>, cudaFuncAttributeMaxDynamicSharedMemorySize, SMEM_128);
    cudaFuncSetAttribute(k_gemm_mma<64>,  cudaFuncAttributeMaxDynamicSharedMemorySize, SMEM_64);

    // one-time side-stream + events (handles only; no device memory)
    static cudaStream_t s2 = nullptr;
    static cudaEvent_t evFork = nullptr, evJoin = nullptr;
    if (s2 == nullptr) {
        cudaStreamCreateWithFlags(&s2, cudaStreamNonBlocking);
        cudaEventCreateWithFlags(&evFork, cudaEventDisableTiming);
        cudaEventCreateWithFlags(&evJoin, cudaEventDisableTiming);
    }

    // fork: weight prep + layer-0 GEMM (independent of graph) on s2
    cudaEventRecord(evFork, 0);
    cudaStreamWaitEvent(s2, evFork, 0);
    k_wprep<<<(3 * 16384 + 8192 + 255) / 256, 256, 0, s2>>>(W0, W1, W2, Wlin);
    k_gemm_mma<128><<<NT, 256, SMEM_128, s2>>>(x, (const uint4*)(whi + 0 * 32768),
                                               (const uint4*)(wlo + 0 * 32768), nullptr, hPtr);
    cudaEventRecord(evJoin, s2);

    // main stream: graph preprocessing (g_cnt zero-invariant restored by k_agg)
    k_count<<<(NEDGES + 255) / 256, 256>>>(col);
    k_scan_fused<<<NSCANBLK, SCAN_BLK>>>();
    k_scatter<<<(NEDGES + 255) / 256, 256>>>(row, col);

    // join
    cudaStreamWaitEvent(0, evJoin, 0);

    const int agg_blocks = (NNODES * 32 + 255) / 256;

    k_agg<<<agg_blocks, 256>>>(hPtr, b0, h2Ptr);
    // layer 1
    k_gemm_mma<128><<<NT, 256, SMEM_128>>>(h2Ptr, (const uint4*)(whi + 1 * 32768),
                                           (const uint4*)(wlo + 1 * 32768), nullptr, hPtr);
    k_agg<<<agg_blocks, 256>>>(hPtr, b1, h2Ptr);
    // layer 2
    k_gemm_mma<128><<<NT, 256, SMEM_128>>>(h2Ptr, (const uint4*)(whi + 2 * 32768),
                                           (const uint4*)(wlo + 2 * 32768), nullptr, hPtr);
    k_agg<<<agg_blocks, 256>>>(hPtr, b2, h2Ptr);
    // head
    k_gemm_mma<64><<<NT, 256, SMEM_64>>>(h2Ptr, (const uint4*)(whi + 3 * 32768),
                                         (const uint4*)(wlo + 3 * 32768), blin, out);
}